// round 1
// baseline (speedup 1.0000x reference)
#include <cuda_runtime.h>
#include <cstdint>

// project_C_shape_simple — the reference's SVD is dead code:
//   rot = Vh^T @ Vh == Identity (det(Vh^T Vh) == 1), so
//   delta_pos = (w/compliance) * (init - (x - com))
//   out = x + delta_pos ;  L_last passes through unchanged.
//
// Pure streaming kernel: 1 thread per (constraint, particle), 16-lane
// butterfly reduction for the mass-weighted center of mass.

static constexpr int P = 16;

__global__ void project_shape_kernel(
    const float* __restrict__ V_predict,    // [N,3]
    const float* __restrict__ V_w,          // [N,1]
    const float* __restrict__ V_mass,       // [N,1]
    const int*   __restrict__ C_shape,      // [C,P]
    const float* __restrict__ C_init,       // [C,P,3]
    const float* __restrict__ V_comp,       // [N,1]
    float*       __restrict__ out,          // [N,3]
    int total)                              // C*P
{
    int slot = blockIdx.x * blockDim.x + threadIdx.x;   // (c, p) flattened
    if (slot >= total) return;

    int i = C_shape[slot];                  // vertex id (disjoint partition)

    // predicted position + mass for this particle
    float px = V_predict[3 * i + 0];
    float py = V_predict[3 * i + 1];
    float pz = V_predict[3 * i + 2];
    float m  = V_mass[i];

    // mass-weighted sums over the 16-lane constraint group.
    // xor offsets 8,4,2,1 never cross a 16-lane boundary.
    float sx = m * px, sy = m * py, sz = m * pz, sm = m;
    #pragma unroll
    for (int off = 8; off > 0; off >>= 1) {
        sx += __shfl_xor_sync(0xffffffffu, sx, off);
        sy += __shfl_xor_sync(0xffffffffu, sy, off);
        sz += __shfl_xor_sync(0xffffffffu, sz, off);
        sm += __shfl_xor_sync(0xffffffffu, sm, off);
    }
    float inv_sm = 1.0f / sm;
    float comx = sx * inv_sm;
    float comy = sy * inv_sm;
    float comz = sz * inv_sm;

    // init shape (indexed by slot — [C,P,3] layout, contiguous)
    float ix = C_init[3 * slot + 0];
    float iy = C_init[3 * slot + 1];
    float iz = C_init[3 * slot + 2];

    // stiffness * inverse mass
    float k = V_w[i] / V_comp[i];

    // delta_x = rot@init - local_pred, rot == I  =>  init - (p - com)
    float ox = fmaf(k, ix - (px - comx), px);
    float oy = fmaf(k, iy - (py - comy), py);
    float oz = fmaf(k, iz - (pz - comz), pz);

    out[3 * i + 0] = ox;
    out[3 * i + 1] = oy;
    out[3 * i + 2] = oz;
}

extern "C" void kernel_launch(void* const* d_in, const int* in_sizes, int n_in,
                              void* d_out, int out_size)
{
    const float* V_predict = (const float*)d_in[0];   // [N,3]
    const float* L_last    = (const float*)d_in[1];   // [C,1]
    const float* V_w       = (const float*)d_in[2];   // [N,1]
    const float* V_mass    = (const float*)d_in[3];   // [N,1]
    const int*   C_shape   = (const int*)  d_in[4];   // [C,P]
    const float* C_init    = (const float*)d_in[5];   // [C,P,3]
    const float* V_comp    = (const float*)d_in[6];   // [N,1]
    float* out = (float*)d_out;

    int n_vp   = in_sizes[0];      // N*3
    int n_last = in_sizes[1];      // C
    int total  = in_sizes[4];      // C*P  (= N)

    int threads = 256;
    int blocks  = (total + threads - 1) / threads;
    project_shape_kernel<<<blocks, threads>>>(
        V_predict, V_w, V_mass, C_shape, C_init, V_comp, out, total);

    // second output: L_last passthrough, appended after V_predict_new
    if (out_size >= n_vp + n_last) {
        cudaMemcpyAsync(out + n_vp, L_last, (size_t)n_last * sizeof(float),
                        cudaMemcpyDeviceToDevice);
    }
}